// round 1
// baseline (speedup 1.0000x reference)
#include <cuda_runtime.h>
#include <math.h>

#define N_ 16384
#define M_ 1024
#define D_ 256
#define EPS_ 1e-6f

// Scratch (allocations are forbidden; device globals are the sanctioned path)
__device__ float g_wx[N_ * D_];   // x * feature_weights          (16 MB)
__device__ float g_wp[M_ * D_];   // prototypes * feature_weights ( 1 MB)
__device__ float g_xn[N_];        // ||wx_n||^2
__device__ float g_pn[M_];        // ||wp_m||^2

// ---------------------------------------------------------------------------
// Prep: fold feature_weights in, compute squared row norms.
// One block per row, 256 threads == D.
// ---------------------------------------------------------------------------
__global__ void prep_kernel(const float* __restrict__ src,
                            const float* __restrict__ fw, int which) {
    const int r = blockIdx.x;
    const int d = threadIdx.x;
    float* dst = which ? g_wp : g_wx;
    float* nrm = which ? g_pn : g_xn;

    float v = src[r * D_ + d] * fw[d];
    dst[r * D_ + d] = v;

    float s = v * v;
#pragma unroll
    for (int o = 16; o > 0; o >>= 1)
        s += __shfl_xor_sync(0xffffffffu, s, o);

    __shared__ float red[8];
    if ((d & 31) == 0) red[d >> 5] = s;
    __syncthreads();
    if (d == 0) {
        float t = 0.f;
#pragma unroll
        for (int i = 0; i < 8; i++) t += red[i];
        nrm[r] = t;
    }
}

// ---------------------------------------------------------------------------
// GEMM: C[n][m] = dot(wx[n], wp[m]) with fused distance/similarity epilogue.
// 128x128 block tile, BK=16, 256 threads, 8x8 register tile, double-buffered.
// ---------------------------------------------------------------------------
#define BM 128
#define BN 128
#define BK 16
#define NT (D_ / BK)

__global__ __launch_bounds__(256, 2)
void gemm_kernel(const float* __restrict__ temp_p, float* __restrict__ out) {
    __shared__ float As[2][BK][BM];
    __shared__ float Bs[2][BK][BN];

    const int tid = threadIdx.x;
    const int tx = tid & 15;   // -> 8 cols each
    const int ty = tid >> 4;   // -> 8 rows each
    const int bm = blockIdx.y * BM;   // offset in N
    const int bn = blockIdx.x * BN;   // offset in M

    // Tile load mapping: 128 rows * 4 float4 per row = 512 float4; 2 per thread.
    const int f0 = tid;
    const int f1 = tid + 256;
    const int ar0 = f0 >> 2, ak0 = (f0 & 3) * 4;
    const int ar1 = f1 >> 2, ak1 = (f1 & 3) * 4;

    const float* Ag = g_wx + (size_t)bm * D_;
    const float* Bg = g_wp + (size_t)bn * D_;

    float4 a_ld0, a_ld1, b_ld0, b_ld1;

    // Prologue: fetch tile 0 -> buffer 0 (transposed to [k][row])
    a_ld0 = *(const float4*)(Ag + ar0 * D_ + ak0);
    a_ld1 = *(const float4*)(Ag + ar1 * D_ + ak1);
    b_ld0 = *(const float4*)(Bg + ar0 * D_ + ak0);
    b_ld1 = *(const float4*)(Bg + ar1 * D_ + ak1);

    As[0][ak0 + 0][ar0] = a_ld0.x; As[0][ak0 + 1][ar0] = a_ld0.y;
    As[0][ak0 + 2][ar0] = a_ld0.z; As[0][ak0 + 3][ar0] = a_ld0.w;
    As[0][ak1 + 0][ar1] = a_ld1.x; As[0][ak1 + 1][ar1] = a_ld1.y;
    As[0][ak1 + 2][ar1] = a_ld1.z; As[0][ak1 + 3][ar1] = a_ld1.w;
    Bs[0][ak0 + 0][ar0] = b_ld0.x; Bs[0][ak0 + 1][ar0] = b_ld0.y;
    Bs[0][ak0 + 2][ar0] = b_ld0.z; Bs[0][ak0 + 3][ar0] = b_ld0.w;
    Bs[0][ak1 + 0][ar1] = b_ld1.x; Bs[0][ak1 + 1][ar1] = b_ld1.y;
    Bs[0][ak1 + 2][ar1] = b_ld1.z; Bs[0][ak1 + 3][ar1] = b_ld1.w;
    __syncthreads();

    float acc[8][8];
#pragma unroll
    for (int i = 0; i < 8; i++)
#pragma unroll
        for (int j = 0; j < 8; j++) acc[i][j] = 0.f;

    for (int kt = 0; kt < NT; ++kt) {
        const int cur = kt & 1;

        if (kt + 1 < NT) {
            const float* Ag2 = Ag + (kt + 1) * BK;
            const float* Bg2 = Bg + (kt + 1) * BK;
            a_ld0 = *(const float4*)(Ag2 + ar0 * D_ + ak0);
            a_ld1 = *(const float4*)(Ag2 + ar1 * D_ + ak1);
            b_ld0 = *(const float4*)(Bg2 + ar0 * D_ + ak0);
            b_ld1 = *(const float4*)(Bg2 + ar1 * D_ + ak1);
        }

        float a_frag[8], b_frag[8];
#pragma unroll
        for (int k = 0; k < BK; ++k) {
#pragma unroll
            for (int i = 0; i < 8; i++) a_frag[i] = As[cur][k][ty * 8 + i];
#pragma unroll
            for (int j = 0; j < 8; j++) b_frag[j] = Bs[cur][k][tx * 8 + j];
#pragma unroll
            for (int i = 0; i < 8; i++)
#pragma unroll
                for (int j = 0; j < 8; j++)
                    acc[i][j] += a_frag[i] * b_frag[j];
        }

        if (kt + 1 < NT) {
            const int nxt = cur ^ 1;
            As[nxt][ak0 + 0][ar0] = a_ld0.x; As[nxt][ak0 + 1][ar0] = a_ld0.y;
            As[nxt][ak0 + 2][ar0] = a_ld0.z; As[nxt][ak0 + 3][ar0] = a_ld0.w;
            As[nxt][ak1 + 0][ar1] = a_ld1.x; As[nxt][ak1 + 1][ar1] = a_ld1.y;
            As[nxt][ak1 + 2][ar1] = a_ld1.z; As[nxt][ak1 + 3][ar1] = a_ld1.w;
            Bs[nxt][ak0 + 0][ar0] = b_ld0.x; Bs[nxt][ak0 + 1][ar0] = b_ld0.y;
            Bs[nxt][ak0 + 2][ar0] = b_ld0.z; Bs[nxt][ak0 + 3][ar0] = b_ld0.w;
            Bs[nxt][ak1 + 0][ar1] = b_ld1.x; Bs[nxt][ak1 + 1][ar1] = b_ld1.y;
            Bs[nxt][ak1 + 2][ar1] = b_ld1.z; Bs[nxt][ak1 + 3][ar1] = b_ld1.w;
        }
        __syncthreads();
    }

    // Epilogue: sq = ||wx||^2 + ||wp||^2 - 2*dot ; dist = sqrt(max(sq,0)+eps);
    // sim = exp(-T*dist). sims -> out[0:N*M], dists -> out[N*M:2*N*M].
    const float temp = __ldg(temp_p);
    float xn_r[8], pn_c[8];
#pragma unroll
    for (int i = 0; i < 8; i++) xn_r[i] = g_xn[bm + ty * 8 + i];
#pragma unroll
    for (int j = 0; j < 8; j++) pn_c[j] = g_pn[bn + tx * 8 + j];

    float* sim_out  = out;
    float* dist_out = out + (size_t)N_ * M_;

#pragma unroll
    for (int i = 0; i < 8; i++) {
        const int row = bm + ty * 8 + i;
        float sim[8], dst[8];
#pragma unroll
        for (int j = 0; j < 8; j++) {
            float sq = xn_r[i] + pn_c[j] - 2.0f * acc[i][j];
            float d  = sqrtf(fmaxf(sq, 0.0f) + EPS_);
            dst[j] = d;
            sim[j] = __expf(-temp * d);
        }
        const size_t base = (size_t)row * M_ + bn + tx * 8;
        *(float4*)(sim_out  + base)     = make_float4(sim[0], sim[1], sim[2], sim[3]);
        *(float4*)(sim_out  + base + 4) = make_float4(sim[4], sim[5], sim[6], sim[7]);
        *(float4*)(dist_out + base)     = make_float4(dst[0], dst[1], dst[2], dst[3]);
        *(float4*)(dist_out + base + 4) = make_float4(dst[4], dst[5], dst[6], dst[7]);
    }
}

// ---------------------------------------------------------------------------
extern "C" void kernel_launch(void* const* d_in, const int* in_sizes, int n_in,
                              void* d_out, int out_size) {
    const float* x    = (const float*)d_in[0];
    const float* p    = (const float*)d_in[1];
    const float* fw   = (const float*)d_in[2];
    const float* temp = (const float*)d_in[3];
    float* out = (float*)d_out;

    prep_kernel<<<N_, 256>>>(x, fw, 0);
    prep_kernel<<<M_, 256>>>(p, fw, 1);
    gemm_kernel<<<dim3(M_ / BN, N_ / BM), 256>>>(temp, out);
}

// round 5
// speedup vs baseline: 3.7460x; 3.7460x over previous
#include <cuda_runtime.h>
#include <cuda_fp16.h>
#include <math.h>
#include <stdint.h>

#define N_ 16384
#define M_ 1024
#define D_ 256
#define EPS_ 1e-6f

// ---------------------------------------------------------------------------
// Scratch (device globals; allocations are forbidden)
// ---------------------------------------------------------------------------
__device__ __half g_xh[N_ * D_];   // fp16(x * fw)           8 MB
__device__ __half g_ph[M_ * D_];   // fp16(prototypes * fw)  0.5 MB
__device__ float  g_xn[N_];        // exact fp32 ||wx||^2
__device__ float  g_pn[M_];

// ---------------------------------------------------------------------------
// Helpers (sm_80-era PTX only: mma.sync + cp.async; NO tcgen05/cluster)
// ---------------------------------------------------------------------------
__device__ __forceinline__ uint32_t smem_u32(const void* p) {
    uint32_t a;
    asm("{ .reg .u64 t; cvta.to.shared.u64 t, %1; cvt.u32.u64 %0, t; }" : "=r"(a) : "l"(p));
    return a;
}
#define CP_ASYNC16(saddr, gptr) \
    asm volatile("cp.async.cg.shared.global [%0], [%1], 16;" :: "r"(saddr), "l"(gptr))
#define CP_COMMIT() asm volatile("cp.async.commit_group;" ::: "memory")
#define CP_WAIT(n)  asm volatile("cp.async.wait_group %0;" :: "n"(n) : "memory")
#define LDS32(r, addr) asm volatile("ld.shared.b32 %0, [%1];" : "=r"(r) : "r"(addr))

__device__ __forceinline__ void mma16816(float c[4], const uint32_t a[4], const uint32_t b[2]) {
    asm volatile(
        "mma.sync.aligned.m16n8k16.row.col.f32.f16.f16.f32 "
        "{%0,%1,%2,%3}, {%4,%5,%6,%7}, {%8,%9}, {%0,%1,%2,%3};"
        : "+f"(c[0]), "+f"(c[1]), "+f"(c[2]), "+f"(c[3])
        : "r"(a[0]), "r"(a[1]), "r"(a[2]), "r"(a[3]), "r"(b[0]), "r"(b[1]));
}

// ---------------------------------------------------------------------------
// Prep: fold feature_weights, fp16 convert, exact fp32 row norms.
// One warp per row (D=256 -> 8 elems/lane).
// ---------------------------------------------------------------------------
__global__ void prep_kernel(const float* __restrict__ src, const float* __restrict__ fw,
                            int which, int rows) {
    const int w = blockIdx.x * 8 + (threadIdx.x >> 5);
    const int l = threadIdx.x & 31;
    if (w >= rows) return;
    __half* dst = which ? g_ph : g_xh;
    float*  nrm = which ? g_pn : g_xn;

    const float4* s4 = (const float4*)(src + (size_t)w * D_) + l * 2;
    const float4* f4 = (const float4*)fw + l * 2;
    float4 a0 = s4[0], a1 = s4[1];
    float4 w0 = f4[0], w1 = f4[1];
    float v[8] = {a0.x * w0.x, a0.y * w0.y, a0.z * w0.z, a0.w * w0.w,
                  a1.x * w1.x, a1.y * w1.y, a1.z * w1.z, a1.w * w1.w};
    __align__(16) __half h[8];
    float s = 0.f;
#pragma unroll
    for (int i = 0; i < 8; i++) {
        s += v[i] * v[i];
        h[i] = __float2half(v[i]);
    }
    *(uint4*)(dst + (size_t)w * D_ + l * 8) = *(uint4*)h;
#pragma unroll
    for (int o = 16; o > 0; o >>= 1) s += __shfl_xor_sync(0xffffffffu, s, o);
    if (l == 0) nrm[w] = s;
}

// ---------------------------------------------------------------------------
// GEMM: 128x128 CTA tile, BK=64, 2-stage cp.async pipeline, 8 warps (4x2),
// warp tile 32x64 via m16n8k16 (2 m-tiles x 8 n-tiles). Fused epilogue.
// SMEM rows padded to 144B: fragment quad q hits banks {4q..4q+3} -> conflict-free.
// ---------------------------------------------------------------------------
#define BM 128
#define BN 128
#define BKT 64
#define NKT (D_ / BKT)
#define ROW_BYTES 144
#define TILE_BYTES (128 * ROW_BYTES)       // 18432 per operand
#define STAGE_BYTES (2 * TILE_BYTES)       // A + B
#define SMEM_TOTAL (2 * STAGE_BYTES)       // 73728

__global__ __launch_bounds__(256, 2)
void gemm_kernel(const float* __restrict__ temp_p, float* __restrict__ out) {
    extern __shared__ char smem[];
    const uint32_t sbase = smem_u32(smem);
    const int tid = threadIdx.x;
    const int wid = tid >> 5, lane = tid & 31;
    const int bm = blockIdx.y * BM;
    const int bn = blockIdx.x * BN;
    const int wm = wid & 3;   // 4 warps along M (32 rows each)
    const int wn = wid >> 2;  // 2 warps along N (64 cols each)
    const int lq = lane >> 2;         // 0..7
    const int lr = (lane & 3);        // 0..3

    // gmem bases (bytes): row stride = D_*2 = 512
    const char* gA = (const char*)(g_xh + (size_t)bm * D_);
    const char* gB = (const char*)(g_ph + (size_t)bn * D_);

    // tile loader: 128 rows x 8 x 16B per operand; 256 threads -> 4 chunks each
    auto load_stage = [&](int kt, int s) {
        const uint32_t sA = sbase + s * STAGE_BYTES;
        const uint32_t sB = sA + TILE_BYTES;
        const int kbyte = kt * (BKT * 2);
#pragma unroll
        for (int t = 0; t < 4; t++) {
            const int idx = tid + t * 256;
            const int row = idx >> 3, ch = idx & 7;
            const int so = row * ROW_BYTES + ch * 16;
            const int go = row * 512 + kbyte + ch * 16;
            CP_ASYNC16(sA + so, gA + go);
            CP_ASYNC16(sB + so, gB + go);
        }
    };

    float c[2][8][4];
#pragma unroll
    for (int mt = 0; mt < 2; mt++)
#pragma unroll
        for (int nt = 0; nt < 8; nt++)
#pragma unroll
            for (int j = 0; j < 4; j++) c[mt][nt][j] = 0.f;

    load_stage(0, 0);
    CP_COMMIT();

    for (int kt = 0; kt < NKT; kt++) {
        if (kt + 1 < NKT) {
            load_stage(kt + 1, (kt + 1) & 1);
            CP_COMMIT();
            CP_WAIT(1);
        } else {
            CP_WAIT(0);
        }
        __syncthreads();

        const uint32_t stg = sbase + (kt & 1) * STAGE_BYTES;
        const uint32_t aAddr = stg + (wm * 32 + lq) * ROW_BYTES + lr * 4;
        const uint32_t bAddr = stg + TILE_BYTES + (wn * 64 + lq) * ROW_BYTES + lr * 4;

#pragma unroll
        for (int ks = 0; ks < 4; ks++) {
            uint32_t a[2][4], b[8][2];
#pragma unroll
            for (int mt = 0; mt < 2; mt++) {
                const uint32_t ad = aAddr + mt * 16 * ROW_BYTES + ks * 32;
                LDS32(a[mt][0], ad);
                LDS32(a[mt][1], ad + 8 * ROW_BYTES);
                LDS32(a[mt][2], ad + 16);
                LDS32(a[mt][3], ad + 8 * ROW_BYTES + 16);
            }
#pragma unroll
            for (int nt = 0; nt < 8; nt++) {
                const uint32_t bd = bAddr + nt * 8 * ROW_BYTES + ks * 32;
                LDS32(b[nt][0], bd);
                LDS32(b[nt][1], bd + 16);
            }
#pragma unroll
            for (int mt = 0; mt < 2; mt++)
#pragma unroll
                for (int nt = 0; nt < 8; nt++)
                    mma16816(c[mt][nt], a[mt], b[nt]);
        }
        __syncthreads();
    }

    // ---- fused epilogue: sq -> dist -> sim, float2 stores ----
    const float temp = __ldg(temp_p);
    float xn[2][2], pn[8][2];
#pragma unroll
    for (int mt = 0; mt < 2; mt++) {
        const int r = bm + wm * 32 + mt * 16 + lq;
        xn[mt][0] = g_xn[r];
        xn[mt][1] = g_xn[r + 8];
    }
#pragma unroll
    for (int nt = 0; nt < 8; nt++) {
        const int cc = bn + wn * 64 + nt * 8 + lr * 2;
        pn[nt][0] = g_pn[cc];
        pn[nt][1] = g_pn[cc + 1];
    }

    float* sim_out = out;
    float* dst_out = out + (size_t)N_ * M_;

#pragma unroll
    for (int mt = 0; mt < 2; mt++) {
#pragma unroll
        for (int p = 0; p < 2; p++) {     // row within m-tile: r or r+8
            const int row = bm + wm * 32 + mt * 16 + p * 8 + lq;
            const size_t rbase = (size_t)row * M_;
#pragma unroll
            for (int nt = 0; nt < 8; nt++) {
                const int col = bn + wn * 64 + nt * 8 + lr * 2;
                float2 sv, dv;
#pragma unroll
                for (int j = 0; j < 2; j++) {
                    const float dot = c[mt][nt][p * 2 + j];
                    const float sq = xn[mt][p] + pn[nt][j] - 2.0f * dot;
                    const float d = sqrtf(fmaxf(sq, 0.0f) + EPS_);
                    ((float*)&dv)[j] = d;
                    ((float*)&sv)[j] = __expf(-temp * d);
                }
                *(float2*)(sim_out + rbase + col) = sv;
                *(float2*)(dst_out + rbase + col) = dv;
            }
        }
    }
}

// ---------------------------------------------------------------------------
extern "C" void kernel_launch(void* const* d_in, const int* in_sizes, int n_in,
                              void* d_out, int out_size) {
    const float* x    = (const float*)d_in[0];
    const float* p    = (const float*)d_in[1];
    const float* fw   = (const float*)d_in[2];
    const float* temp = (const float*)d_in[3];
    float* out = (float*)d_out;

    cudaFuncSetAttribute(gemm_kernel, cudaFuncAttributeMaxDynamicSharedMemorySize, SMEM_TOTAL);

    prep_kernel<<<N_ / 8, 256>>>(x, fw, 0, N_);
    prep_kernel<<<M_ / 8, 256>>>(p, fw, 1, M_);
    gemm_kernel<<<dim3(M_ / BN, N_ / BM), 256, SMEM_TOTAL>>>(temp, out);
}

// round 6
// speedup vs baseline: 4.2984x; 1.1475x over previous
#include <cuda_runtime.h>
#include <cuda_fp16.h>
#include <math.h>
#include <stdint.h>

#define N_ 16384
#define M_ 1024
#define D_ 256
#define EPS_ 1e-6f

// ---------------------------------------------------------------------------
// Scratch (device globals; allocations are forbidden)
// ---------------------------------------------------------------------------
__device__ __half g_xh[N_ * D_];   // fp16(x * fw)           8 MB
__device__ __half g_ph[M_ * D_];   // fp16(prototypes * fw)  0.5 MB
__device__ float  g_xn[N_];        // exact fp32 ||wx||^2
__device__ float  g_pn[M_];

// ---------------------------------------------------------------------------
// Helpers (family-portable PTX only: mma.sync / ldmatrix / cp.async)
// ---------------------------------------------------------------------------
__device__ __forceinline__ uint32_t smem_u32(const void* p) {
    uint32_t a;
    asm("{ .reg .u64 t; cvta.to.shared.u64 t, %1; cvt.u32.u64 %0, t; }" : "=r"(a) : "l"(p));
    return a;
}
#define CP_ASYNC16(saddr, gptr) \
    asm volatile("cp.async.cg.shared.global [%0], [%1], 16;" :: "r"(saddr), "l"(gptr))
#define CP_COMMIT() asm volatile("cp.async.commit_group;" ::: "memory")
#define CP_WAIT(n)  asm volatile("cp.async.wait_group %0;" :: "n"(n) : "memory")
#define LDSM4(r0, r1, r2, r3, addr) \
    asm volatile("ldmatrix.sync.aligned.m8n8.x4.shared.b16 {%0,%1,%2,%3}, [%4];" \
        : "=r"(r0), "=r"(r1), "=r"(r2), "=r"(r3) : "r"(addr))

__device__ __forceinline__ void mma16816(float c[4], const uint32_t a[4], const uint32_t b[2]) {
    asm volatile(
        "mma.sync.aligned.m16n8k16.row.col.f32.f16.f16.f32 "
        "{%0,%1,%2,%3}, {%4,%5,%6,%7}, {%8,%9}, {%0,%1,%2,%3};"
        : "+f"(c[0]), "+f"(c[1]), "+f"(c[2]), "+f"(c[3])
        : "r"(a[0]), "r"(a[1]), "r"(a[2]), "r"(a[3]), "r"(b[0]), "r"(b[1]));
}

// ---------------------------------------------------------------------------
// Prep (merged x + p): fold fw, fp16 convert, exact fp32 row norms.
// One warp per row; row index < N_ -> x, else -> prototypes.
// ---------------------------------------------------------------------------
__global__ void prep_kernel(const float* __restrict__ x, const float* __restrict__ p,
                            const float* __restrict__ fw) {
    const int w = blockIdx.x * 8 + (threadIdx.x >> 5);
    const int l = threadIdx.x & 31;
    const int isP = (w >= N_);
    const int r = isP ? (w - N_) : w;
    const float* src = isP ? p : x;
    __half* dst = isP ? g_ph : g_xh;
    float*  nrm = isP ? g_pn : g_xn;

    const float4* s4 = (const float4*)(src + (size_t)r * D_) + l * 2;
    const float4* f4 = (const float4*)fw + l * 2;
    float4 a0 = s4[0], a1 = s4[1];
    float4 w0 = f4[0], w1 = f4[1];
    float v[8] = {a0.x * w0.x, a0.y * w0.y, a0.z * w0.z, a0.w * w0.w,
                  a1.x * w1.x, a1.y * w1.y, a1.z * w1.z, a1.w * w1.w};
    __align__(16) __half h[8];
    float s = 0.f;
#pragma unroll
    for (int i = 0; i < 8; i++) {
        s += v[i] * v[i];
        h[i] = __float2half(v[i]);
    }
    *(uint4*)(dst + (size_t)r * D_ + l * 8) = *(uint4*)h;
#pragma unroll
    for (int o = 16; o > 0; o >>= 1) s += __shfl_xor_sync(0xffffffffu, s, o);
    if (l == 0) nrm[r] = s;
}

// ---------------------------------------------------------------------------
// GEMM: 128x128 CTA tile, BK=64, 2-stage cp.async, 8 warps (4x2), warp 32x64.
// ldmatrix.x4 fragment loads; fused sqrt/exp epilogue; streaming stores.
// SMEM rows padded to 144B (conflict-free for ldmatrix phases: banks 4r..4r+3).
// ---------------------------------------------------------------------------
#define BM 128
#define BN 128
#define BKT 64
#define NKT (D_ / BKT)
#define ROW_BYTES 144
#define TILE_BYTES (128 * ROW_BYTES)       // 18432 per operand
#define STAGE_BYTES (2 * TILE_BYTES)
#define SMEM_TOTAL (2 * STAGE_BYTES)       // 73728

__global__ __launch_bounds__(256, 2)
void gemm_kernel(const float* __restrict__ temp_p, float* __restrict__ out) {
    extern __shared__ char smem[];
    const uint32_t sbase = smem_u32(smem);
    const int tid = threadIdx.x;
    const int wid = tid >> 5, lane = tid & 31;
    const int bm = blockIdx.y * BM;
    const int bn = blockIdx.x * BN;
    const int wm = wid & 3;   // 4 warps along M (32 rows)
    const int wn = wid >> 2;  // 2 warps along N (64 cols)
    const int lq = lane >> 2, lr = lane & 3;

    const char* gA = (const char*)(g_xh + (size_t)bm * D_);
    const char* gB = (const char*)(g_ph + (size_t)bn * D_);

    auto load_stage = [&](int kt, int s) {
        const uint32_t sA = sbase + s * STAGE_BYTES;
        const uint32_t sB = sA + TILE_BYTES;
        const int kbyte = kt * (BKT * 2);
#pragma unroll
        for (int t = 0; t < 4; t++) {
            const int idx = tid + t * 256;
            const int row = idx >> 3, ch = idx & 7;
            const int so = row * ROW_BYTES + ch * 16;
            const int go = row * 512 + kbyte + ch * 16;
            CP_ASYNC16(sA + so, gA + go);
            CP_ASYNC16(sB + so, gB + go);
        }
    };

    // ldmatrix per-lane offsets (within stage)
    // A (m16k16, x4): row = wm*32 + (lane&15) [+ mt*16], khalf = (lane>>4)*16B
    const uint32_t aOff = (uint32_t)((wm * 32 + (lane & 15)) * ROW_BYTES + (lane >> 4) * 16);
    // B (two n8k16 tiles, x4): row = wn*64 + (lane>>4)*8 + (lane&7) [+ pair*16],
    // khalf = ((lane>>3)&1)*16B
    const uint32_t bOff = (uint32_t)(TILE_BYTES +
        (wn * 64 + ((lane >> 4) << 3) + (lane & 7)) * ROW_BYTES + ((lane >> 3) & 1) * 16);

    float c[2][8][4];
#pragma unroll
    for (int mt = 0; mt < 2; mt++)
#pragma unroll
        for (int nt = 0; nt < 8; nt++)
#pragma unroll
            for (int j = 0; j < 4; j++) c[mt][nt][j] = 0.f;

    load_stage(0, 0);
    CP_COMMIT();

    for (int kt = 0; kt < NKT; kt++) {
        if (kt + 1 < NKT) {
            load_stage(kt + 1, (kt + 1) & 1);
            CP_COMMIT();
            CP_WAIT(1);
        } else {
            CP_WAIT(0);
        }
        __syncthreads();

        const uint32_t stg = sbase + (kt & 1) * STAGE_BYTES;

#pragma unroll
        for (int ks = 0; ks < 4; ks++) {
            uint32_t a[2][4], b[8][2];
            const uint32_t ksb = ks * 32;
#pragma unroll
            for (int mt = 0; mt < 2; mt++)
                LDSM4(a[mt][0], a[mt][1], a[mt][2], a[mt][3],
                      stg + aOff + mt * (16 * ROW_BYTES) + ksb);
#pragma unroll
            for (int pr = 0; pr < 4; pr++)
                LDSM4(b[2 * pr][0], b[2 * pr][1], b[2 * pr + 1][0], b[2 * pr + 1][1],
                      stg + bOff + pr * (16 * ROW_BYTES) + ksb);
#pragma unroll
            for (int mt = 0; mt < 2; mt++)
#pragma unroll
                for (int nt = 0; nt < 8; nt++)
                    mma16816(c[mt][nt], a[mt], b[nt]);
        }
        __syncthreads();
    }

    // ---- fused epilogue: sq -> dist -> sim; streaming float2 stores ----
    const float temp = __ldg(temp_p);
    float xn[2][2], pn[8][2];
#pragma unroll
    for (int mt = 0; mt < 2; mt++) {
        const int r = bm + wm * 32 + mt * 16 + lq;
        xn[mt][0] = g_xn[r];
        xn[mt][1] = g_xn[r + 8];
    }
#pragma unroll
    for (int nt = 0; nt < 8; nt++) {
        const int cc = bn + wn * 64 + nt * 8 + lr * 2;
        pn[nt][0] = g_pn[cc];
        pn[nt][1] = g_pn[cc + 1];
    }

    float* sim_out = out;
    float* dst_out = out + (size_t)N_ * M_;

#pragma unroll
    for (int mt = 0; mt < 2; mt++) {
#pragma unroll
        for (int p = 0; p < 2; p++) {
            const int row = bm + wm * 32 + mt * 16 + p * 8 + lq;
            const size_t rbase = (size_t)row * M_;
#pragma unroll
            for (int nt = 0; nt < 8; nt++) {
                const int col = bn + wn * 64 + nt * 8 + lr * 2;
                float2 sv, dv;
#pragma unroll
                for (int j = 0; j < 2; j++) {
                    const float dot = c[mt][nt][p * 2 + j];
                    const float sq = xn[mt][p] + pn[nt][j] - 2.0f * dot;
                    const float d = sqrtf(fmaxf(sq, 0.0f) + EPS_);
                    ((float*)&dv)[j] = d;
                    ((float*)&sv)[j] = __expf(-temp * d);
                }
                __stcs((float2*)(sim_out + rbase + col), sv);
                __stcs((float2*)(dst_out + rbase + col), dv);
            }
        }
    }
}

// ---------------------------------------------------------------------------
extern "C" void kernel_launch(void* const* d_in, const int* in_sizes, int n_in,
                              void* d_out, int out_size) {
    const float* x    = (const float*)d_in[0];
    const float* p    = (const float*)d_in[1];
    const float* fw   = (const float*)d_in[2];
    const float* temp = (const float*)d_in[3];
    float* out = (float*)d_out;

    cudaFuncSetAttribute(gemm_kernel, cudaFuncAttributeMaxDynamicSharedMemorySize, SMEM_TOTAL);

    prep_kernel<<<(N_ + M_) / 8, 256>>>(x, p, fw);
    gemm_kernel<<<dim3(M_ / BN, N_ / BM), 256, SMEM_TOTAL>>>(temp, out);
}

// round 8
// speedup vs baseline: 4.3009x; 1.0006x over previous
#include <cuda_runtime.h>
#include <cuda_fp16.h>
#include <math.h>
#include <stdint.h>

#define N_ 16384
#define M_ 1024
#define D_ 256
#define EPS_ 1e-6f

// ---------------------------------------------------------------------------
// Scratch (device globals; allocations are forbidden)
// ---------------------------------------------------------------------------
__device__ __half g_xh[N_ * D_];   // fp16(x * fw)           8 MB
__device__ __half g_ph[M_ * D_];   // fp16(prototypes * fw)  0.5 MB
__device__ float  g_xn[N_];        // exact fp32 ||wx||^2
__device__ float  g_pn[M_];

// ---------------------------------------------------------------------------
// Helpers (family-portable PTX only: mma.sync / ldmatrix / cp.async)
// ---------------------------------------------------------------------------
__device__ __forceinline__ uint32_t smem_u32(const void* p) {
    uint32_t a;
    asm("{ .reg .u64 t; cvta.to.shared.u64 t, %1; cvt.u32.u64 %0, t; }" : "=r"(a) : "l"(p));
    return a;
}
#define CP_ASYNC16(saddr, gptr) \
    asm volatile("cp.async.cg.shared.global [%0], [%1], 16;" :: "r"(saddr), "l"(gptr))
#define CP_COMMIT() asm volatile("cp.async.commit_group;" ::: "memory")
#define CP_WAIT(n)  asm volatile("cp.async.wait_group %0;" :: "n"(n) : "memory")
#define LDSM4(r0, r1, r2, r3, addr) \
    asm volatile("ldmatrix.sync.aligned.m8n8.x4.shared.b16 {%0,%1,%2,%3}, [%4];" \
        : "=r"(r0), "=r"(r1), "=r"(r2), "=r"(r3) : "r"(addr))

__device__ __forceinline__ void mma16816(float c[4], const uint32_t a[4], const uint32_t b[2]) {
    asm volatile(
        "mma.sync.aligned.m16n8k16.row.col.f32.f16.f16.f32 "
        "{%0,%1,%2,%3}, {%4,%5,%6,%7}, {%8,%9}, {%0,%1,%2,%3};"
        : "+f"(c[0]), "+f"(c[1]), "+f"(c[2]), "+f"(c[3])
        : "r"(a[0]), "r"(a[1]), "r"(a[2]), "r"(a[3]), "r"(b[0]), "r"(b[1]));
}

// ---------------------------------------------------------------------------
// Prep (merged x + p): fold fw, fp16 convert, exact fp32 row norms.
// ---------------------------------------------------------------------------
__global__ void prep_kernel(const float* __restrict__ x, const float* __restrict__ p,
                            const float* __restrict__ fw) {
    const int w = blockIdx.x * 8 + (threadIdx.x >> 5);
    const int l = threadIdx.x & 31;
    const int isP = (w >= N_);
    const int r = isP ? (w - N_) : w;
    const float* src = isP ? p : x;
    __half* dst = isP ? g_ph : g_xh;
    float*  nrm = isP ? g_pn : g_xn;

    const float4* s4 = (const float4*)(src + (size_t)r * D_) + l * 2;
    const float4* f4 = (const float4*)fw + l * 2;
    float4 a0 = s4[0], a1 = s4[1];
    float4 w0 = f4[0], w1 = f4[1];
    float v[8] = {a0.x * w0.x, a0.y * w0.y, a0.z * w0.z, a0.w * w0.w,
                  a1.x * w1.x, a1.y * w1.y, a1.z * w1.z, a1.w * w1.w};
    __align__(16) __half h[8];
    float s = 0.f;
#pragma unroll
    for (int i = 0; i < 8; i++) {
        s += v[i] * v[i];
        h[i] = __float2half(v[i]);
    }
    *(uint4*)(dst + (size_t)r * D_ + l * 8) = *(uint4*)h;
#pragma unroll
    for (int o = 16; o > 0; o >>= 1) s += __shfl_xor_sync(0xffffffffu, s, o);
    if (l == 0) nrm[r] = s;
}

// ---------------------------------------------------------------------------
// GEMM: 128x128 CTA tile, BK=64, 3-stage cp.async pipeline (1 sync per ktile),
// 8 warps (4x2), warp 32x64, ldmatrix.x4, fused rsqrt/exp epilogue.
// SMEM rows padded to 144B (conflict-free ldmatrix: banks 4r..4r+3).
// ---------------------------------------------------------------------------
#define BM 128
#define BN 128
#define BKT 64
#define NKT (D_ / BKT)
#define ROW_BYTES 144
#define TILE_BYTES (128 * ROW_BYTES)       // 18432 per operand
#define STAGE_BYTES (2 * TILE_BYTES)       // 36864
#define SMEM_TOTAL (3 * STAGE_BYTES)       // 110592 (2 CTAs/SM: 221KB < 227KB)

__global__ __launch_bounds__(256, 2)
void gemm_kernel(const float* __restrict__ temp_p, float* __restrict__ out) {
    extern __shared__ char smem[];
    const uint32_t sbase = smem_u32(smem);
    const int tid = threadIdx.x;
    const int wid = tid >> 5, lane = tid & 31;
    const int bm = blockIdx.y * BM;
    const int bn = blockIdx.x * BN;
    const int wm = wid & 3;   // 4 warps along M (32 rows)
    const int wn = wid >> 2;  // 2 warps along N (64 cols)
    const int lq = lane >> 2, lr = lane & 3;

    const float temp = __ldg(temp_p);      // hoisted: latency hidden by mainloop

    const char* gA = (const char*)(g_xh + (size_t)bm * D_);
    const char* gB = (const char*)(g_ph + (size_t)bn * D_);

    auto load_stage = [&](int kt, int s) {
        const uint32_t sA = sbase + s * STAGE_BYTES;
        const uint32_t sB = sA + TILE_BYTES;
        const int kbyte = kt * (BKT * 2);
#pragma unroll
        for (int t = 0; t < 4; t++) {
            const int idx = tid + t * 256;
            const int row = idx >> 3, ch = idx & 7;
            const int so = row * ROW_BYTES + ch * 16;
            const int go = row * 512 + kbyte + ch * 16;
            CP_ASYNC16(sA + so, gA + go);
            CP_ASYNC16(sB + so, gB + go);
        }
    };

    // ldmatrix per-lane offsets (within stage)
    const uint32_t aOff = (uint32_t)((wm * 32 + (lane & 15)) * ROW_BYTES + (lane >> 4) * 16);
    const uint32_t bOff = (uint32_t)(TILE_BYTES +
        (wn * 64 + ((lane >> 4) << 3) + (lane & 7)) * ROW_BYTES + ((lane >> 3) & 1) * 16);

    float c[2][8][4];
#pragma unroll
    for (int mt = 0; mt < 2; mt++)
#pragma unroll
        for (int nt = 0; nt < 8; nt++)
#pragma unroll
            for (int j = 0; j < 4; j++) c[mt][nt][j] = 0.f;

    auto compute = [&](int s) {
        const uint32_t stg = sbase + s * STAGE_BYTES;
#pragma unroll
        for (int ks = 0; ks < 4; ks++) {
            uint32_t a[2][4], b[8][2];
            const uint32_t ksb = ks * 32;
#pragma unroll
            for (int mt = 0; mt < 2; mt++)
                LDSM4(a[mt][0], a[mt][1], a[mt][2], a[mt][3],
                      stg + aOff + mt * (16 * ROW_BYTES) + ksb);
#pragma unroll
            for (int pr = 0; pr < 4; pr++)
                LDSM4(b[2 * pr][0], b[2 * pr][1], b[2 * pr + 1][0], b[2 * pr + 1][1],
                      stg + bOff + pr * (16 * ROW_BYTES) + ksb);
#pragma unroll
            for (int mt = 0; mt < 2; mt++)
#pragma unroll
                for (int nt = 0; nt < 8; nt++)
                    mma16816(c[mt][nt], a[mt], b[nt]);
        }
    };

    // ---- 3-stage pipeline, NKT = 4, fully unrolled ----
    load_stage(0, 0); CP_COMMIT();
    load_stage(1, 1); CP_COMMIT();

    CP_WAIT(1); __syncthreads();           // tile 0 ready
    load_stage(2, 2); CP_COMMIT();
    compute(0);

    CP_WAIT(1); __syncthreads();           // tile 1 ready; stage0 free (all read tile0)
    load_stage(3, 0); CP_COMMIT();
    compute(1);

    CP_WAIT(1); __syncthreads();           // tile 2 ready
    compute(2);

    CP_WAIT(0); __syncthreads();           // tile 3 ready
    compute(0);                            // tile 3 lives in stage 0

    // ---- fused epilogue: sq -> dist (rsqrt) -> sim; streaming stores ----
    float xn[2][2], pn[8][2];
#pragma unroll
    for (int mt = 0; mt < 2; mt++) {
        const int r = bm + wm * 32 + mt * 16 + lq;
        xn[mt][0] = g_xn[r];
        xn[mt][1] = g_xn[r + 8];
    }
#pragma unroll
    for (int nt = 0; nt < 8; nt++) {
        const int cc = bn + wn * 64 + nt * 8 + lr * 2;
        pn[nt][0] = g_pn[cc];
        pn[nt][1] = g_pn[cc + 1];
    }

    float* sim_out = out;
    float* dst_out = out + (size_t)N_ * M_;

#pragma unroll
    for (int mt = 0; mt < 2; mt++) {
#pragma unroll
        for (int p = 0; p < 2; p++) {
            const int row = bm + wm * 32 + mt * 16 + p * 8 + lq;
            const size_t rbase = (size_t)row * M_;
#pragma unroll
            for (int nt = 0; nt < 8; nt++) {
                const int col = bn + wn * 64 + nt * 8 + lr * 2;
                float2 sv, dv;
#pragma unroll
                for (int j = 0; j < 2; j++) {
                    const float dot = c[mt][nt][p * 2 + j];
                    const float sq = fmaxf(xn[mt][p] + pn[nt][j] - 2.0f * dot, 0.0f) + EPS_;
                    const float d = sq * rsqrtf(sq);   // sqrt(sq), sq >= eps > 0
                    ((float*)&dv)[j] = d;
                    ((float*)&sv)[j] = __expf(-temp * d);
                }
                __stcs((float2*)(sim_out + rbase + col), sv);
                __stcs((float2*)(dst_out + rbase + col), dv);
            }
        }
    }
}

// ---------------------------------------------------------------------------
extern "C" void kernel_launch(void* const* d_in, const int* in_sizes, int n_in,
                              void* d_out, int out_size) {
    const float* x    = (const float*)d_in[0];
    const float* p    = (const float*)d_in[1];
    const float* fw   = (const float*)d_in[2];
    const float* temp = (const float*)d_in[3];
    float* out = (float*)d_out;

    cudaFuncSetAttribute(gemm_kernel, cudaFuncAttributeMaxDynamicSharedMemorySize, SMEM_TOTAL);

    prep_kernel<<<(N_ + M_) / 8, 256>>>(x, p, fw);
    gemm_kernel<<<dim3(M_ / BN, N_ / BM), 256, SMEM_TOTAL>>>(temp, out);
}